// round 1
// baseline (speedup 1.0000x reference)
#include <cuda_runtime.h>
#include <math.h>

// Problem dims
#define BATCH 32
#define CIN   4
#define HID   64
#define EPS   1e-12f

// Packed weight layout (floats):
//  W0[net] : [tap(4)][i(4)][o(64)]          at net*1024          (2048 total)
//  W1[net] : [tap(5)][i(64)][o(64)]         at 2048  + net*20480 (40960)
//  W2[net] : [tap(5)][i(64)][o(64)]         at 43008 + net*20480 (40960)
//  WO[net] : [i(64)][ch(4)]                 at 83968 + net*256   (512)
#define W0_OFF(net) ((net)*1024)
#define W1_OFF(net) (2048 + (net)*20480)
#define W2_OFF(net) (43008 + (net)*20480)
#define WO_OFF(net) (83968 + (net)*256)
#define WP_TOTAL 84480

__device__ float g_wp[WP_TOTAL];

// Mask-A taps (kr,kc): (0,0),(0,1),(0,2),(1,0)  -> (dr,dc) = (-1,-1),(-1,0),(-1,1),(0,-1)
// Mask-B taps: A + (1,1) center -> + (0,0)
__global__ void repack_kernel(const float* __restrict__ mw0, const float* __restrict__ mw1,
                              const float* __restrict__ mw2, const float* __restrict__ mwo,
                              const float* __restrict__ lw0, const float* __restrict__ lw1,
                              const float* __restrict__ lw2, const float* __restrict__ lwo)
{
    int t = blockIdx.x * blockDim.x + threadIdx.x;
    if (t >= WP_TOTAL) return;
    const int krA[4] = {0,0,0,1}, kcA[4] = {0,1,2,0};
    const int krB[5] = {0,0,0,1,1}, kcB[5] = {0,1,2,0,1};
    if (t < 2048) {
        int net = t / 1024, rem = t % 1024;
        int tap = rem / 256, i = (rem / 64) & 3, o = rem & 63;
        const float* w = net ? lw0 : mw0;
        g_wp[t] = w[((o * CIN + i) * 3 + krA[tap]) * 3 + kcA[tap]];
    } else if (t < 43008) {
        int u = t - 2048;
        int net = u / 20480, rem = u % 20480;
        int tap = rem / 4096, i = (rem / 64) & 63, o = rem & 63;
        const float* w = net ? lw1 : mw1;
        g_wp[t] = w[((o * HID + i) * 3 + krB[tap]) * 3 + kcB[tap]];
    } else if (t < 83968) {
        int u = t - 43008;
        int net = u / 20480, rem = u % 20480;
        int tap = rem / 4096, i = (rem / 64) & 63, o = rem & 63;
        const float* w = net ? lw2 : mw2;
        g_wp[t] = w[((o * HID + i) * 3 + krB[tap]) * 3 + kcB[tap]];
    } else {
        int u = t - 83968;
        int net = u / 256, rem = u % 256;
        int i = rem / 4, ch = rem & 3;
        const float* w = net ? lwo : mwo;
        g_wp[t] = w[ch * HID + i];
    }
}

__device__ __forceinline__ float elu1(float v) {
    return v > 0.f ? v : (expf(v) - 1.f);
}

// Shared mem layout (floats)
//  s_h0   : [2][64px][64ch]  8192  @ 0
//  s_h1   : [2][64px][64ch]  8192  @ 8192
//  s_y    : [4ch][64px]       256  @ 16384
//  s_x    : [4ch][64px]       256  @ 16640
//  s_b0   : [2][64]           128  @ 16896
//  s_b1   : [2][64]           128  @ 17024
//  s_b2   : [2][64]           128  @ 17152
//  s_bo   : [2][4]              8  @ 17280
//  s_mlv  : [2][4a][4ch]       32  @ 17288
//  s_lsb  : [4ch][64px]       256  @ 17320
#define SMEM_FLOATS 17576
#define SMEM_BYTES  (SMEM_FLOATS * 4)

__global__ void __launch_bounds__(256, 1)
made_kernel(const float* __restrict__ x,
            const float* __restrict__ mb0, const float* __restrict__ mb1,
            const float* __restrict__ mb2, const float* __restrict__ mbo,
            const float* __restrict__ lb0, const float* __restrict__ lb1,
            const float* __restrict__ lb2, const float* __restrict__ lbo,
            float* __restrict__ out)
{
    extern __shared__ float sm[];
    float* s_h0  = sm;
    float* s_h1  = sm + 8192;
    float* s_y   = sm + 16384;
    float* s_x   = sm + 16640;
    float* s_b0  = sm + 16896;
    float* s_b1  = sm + 17024;
    float* s_b2  = sm + 17152;
    float* s_bo  = sm + 17280;
    float* s_mlv = sm + 17288;
    float* s_lsb = sm + 17320;

    const int b = blockIdx.x;
    const int tid = threadIdx.x;
    const int lane = tid & 31, wid = tid >> 5;

    // init
    s_x[tid] = x[b * 256 + tid];
    s_y[tid] = 0.f;
    if (tid < 64) {
        s_b0[tid] = mb0[tid]; s_b0[64 + tid] = lb0[tid];
        s_b1[tid] = mb1[tid]; s_b1[64 + tid] = lb1[tid];
        s_b2[tid] = mb2[tid]; s_b2[64 + tid] = lb2[tid];
    }
    if (tid < 4) { s_bo[tid] = mbo[tid]; s_bo[4 + tid] = lbo[tid]; }
    __syncthreads();

    const int dRA[4] = {-1,-1,-1, 0}, dCA[4] = {-1, 0, 1,-1};
    const int dRB[5] = {-1,-1,-1, 0, 0}, dCB[5] = {-1, 0, 1,-1, 0};

    for (int s = 0; s < 22; s++) {
        int rlo = max(0, (s - 6) / 2);
        int rhi = min(7, s / 2);
        int npix = rhi - rlo + 1;
        int nunits = npix * 2;

        int net = 0, r = 0, c = 0, p = 0, aslot = 0, active = 0;
        if (wid < nunits) {
            active = 1;
            aslot = wid >> 1; net = wid & 1;
            r = rlo + aslot; c = s - 2 * r; p = r * 8 + c;
        }

        // ---- layer 0 (mask A, C=4 -> 64) ----
        if (active) {
            int o = lane * 2;
            float2 acc = make_float2(s_b0[net * 64 + o], s_b0[net * 64 + o + 1]);
            const float* wb = g_wp + W0_OFF(net);
            #pragma unroll
            for (int tap = 0; tap < 4; tap++) {
                int rr = r + dRA[tap], cc = c + dCA[tap];
                if (rr >= 0 && cc >= 0 && cc < 8) {
                    int pt = rr * 8 + cc;
                    #pragma unroll
                    for (int i = 0; i < 4; i++) {
                        float2 wv = *(const float2*)(wb + (tap * 4 + i) * 64 + o);
                        float yv = s_y[i * 64 + pt];
                        acc.x += wv.x * yv; acc.y += wv.y * yv;
                    }
                }
            }
            acc.x = elu1(acc.x); acc.y = elu1(acc.y);
            *(float2*)(s_h0 + (net * 64 + p) * 64 + o) = acc;
        }
        __syncthreads();

        // ---- layer 1 (mask B, 64 -> 64) ----
        int half = lane >> 4;
        int o4 = (lane & 15) * 4;
        if (active) {
            float a0 = 0.f, a1 = 0.f, a2 = 0.f, a3 = 0.f;
            const float* wb = g_wp + W1_OFF(net);
            #pragma unroll
            for (int tap = 0; tap < 5; tap++) {
                int rr = r + dRB[tap], cc = c + dCB[tap];
                if (rr >= 0 && cc >= 0 && cc < 8) {
                    int pt = rr * 8 + cc;
                    const float* hp = s_h0 + (net * 64 + pt) * 64;
                    const float* wt = wb + tap * 4096 + o4;
                    #pragma unroll 8
                    for (int ii = half; ii < 64; ii += 2) {
                        float4 wv = *(const float4*)(wt + ii * 64);
                        float hv = hp[ii];
                        a0 += wv.x * hv; a1 += wv.y * hv;
                        a2 += wv.z * hv; a3 += wv.w * hv;
                    }
                }
            }
            a0 += __shfl_down_sync(0xffffffffu, a0, 16);
            a1 += __shfl_down_sync(0xffffffffu, a1, 16);
            a2 += __shfl_down_sync(0xffffffffu, a2, 16);
            a3 += __shfl_down_sync(0xffffffffu, a3, 16);
            if (half == 0) {
                a0 = elu1(a0 + s_b1[net * 64 + o4 + 0]);
                a1 = elu1(a1 + s_b1[net * 64 + o4 + 1]);
                a2 = elu1(a2 + s_b1[net * 64 + o4 + 2]);
                a3 = elu1(a3 + s_b1[net * 64 + o4 + 3]);
                *(float4*)(s_h1 + (net * 64 + p) * 64 + o4) = make_float4(a0, a1, a2, a3);
            }
        }
        __syncthreads();

        // ---- layer 2 (mask B, 64 -> 64) + 1x1 output conv ----
        if (active) {
            float a0 = 0.f, a1 = 0.f, a2 = 0.f, a3 = 0.f;
            const float* wb = g_wp + W2_OFF(net);
            #pragma unroll
            for (int tap = 0; tap < 5; tap++) {
                int rr = r + dRB[tap], cc = c + dCB[tap];
                if (rr >= 0 && cc >= 0 && cc < 8) {
                    int pt = rr * 8 + cc;
                    const float* hp = s_h1 + (net * 64 + pt) * 64;
                    const float* wt = wb + tap * 4096 + o4;
                    #pragma unroll 8
                    for (int ii = half; ii < 64; ii += 2) {
                        float4 wv = *(const float4*)(wt + ii * 64);
                        float hv = hp[ii];
                        a0 += wv.x * hv; a1 += wv.y * hv;
                        a2 += wv.z * hv; a3 += wv.w * hv;
                    }
                }
            }
            a0 += __shfl_down_sync(0xffffffffu, a0, 16);
            a1 += __shfl_down_sync(0xffffffffu, a1, 16);
            a2 += __shfl_down_sync(0xffffffffu, a2, 16);
            a3 += __shfl_down_sync(0xffffffffu, a3, 16);

            float px = 0.f, py = 0.f, pz = 0.f, pw = 0.f;
            if (half == 0) {
                float h2v[4];
                h2v[0] = elu1(a0 + s_b2[net * 64 + o4 + 0]);
                h2v[1] = elu1(a1 + s_b2[net * 64 + o4 + 1]);
                h2v[2] = elu1(a2 + s_b2[net * 64 + o4 + 2]);
                h2v[3] = elu1(a3 + s_b2[net * 64 + o4 + 3]);
                const float* wo = g_wp + WO_OFF(net);
                #pragma unroll
                for (int k = 0; k < 4; k++) {
                    float4 w4 = *(const float4*)(wo + (o4 + k) * 4);
                    px += h2v[k] * w4.x; py += h2v[k] * w4.y;
                    pz += h2v[k] * w4.z; pw += h2v[k] * w4.w;
                }
            }
            #pragma unroll
            for (int off = 8; off >= 1; off >>= 1) {
                px += __shfl_down_sync(0xffffffffu, px, off);
                py += __shfl_down_sync(0xffffffffu, py, off);
                pz += __shfl_down_sync(0xffffffffu, pz, off);
                pw += __shfl_down_sync(0xffffffffu, pw, off);
            }
            if (lane == 0) {
                float* o = s_mlv + (net * 4 + aslot) * 4;
                o[0] = px + s_bo[net * 4 + 0];
                o[1] = py + s_bo[net * 4 + 1];
                o[2] = pz + s_bo[net * 4 + 2];
                o[3] = pw + s_bo[net * 4 + 3];
            }
        }
        __syncthreads();

        // ---- y update ----
        if (tid < npix * 4) {
            int a = tid >> 2, ch = tid & 3;
            int rr = rlo + a, cc = s - 2 * rr;
            int pp = rr * 8 + cc;
            float mu = s_mlv[(0 * 4 + a) * 4 + ch];
            float ls = 0.5f * s_mlv[(1 * 4 + a) * 4 + ch];
            float yv = (s_x[ch * 64 + pp] - mu) / (expf(ls) + EPS);
            s_y[ch * 64 + pp] = yv;
            s_lsb[ch * 64 + pp] = ls;
        }
        __syncthreads();
    }

    // write y
    out[b * 256 + tid] = s_y[tid];
    // deterministic serial logstd sum per batch
    if (tid == 0) {
        float acc = 0.f;
        for (int i = 0; i < 256; i++) acc += s_lsb[i];
        out[BATCH * 256 + b] = acc;
    }
}

extern "C" void kernel_launch(void* const* d_in, const int* in_sizes, int n_in,
                              void* d_out, int out_size)
{
    (void)in_sizes; (void)n_in; (void)out_size;
    const float* x   = (const float*)d_in[0];
    const float* mw0 = (const float*)d_in[1];
    const float* mb0 = (const float*)d_in[2];
    const float* mw1 = (const float*)d_in[3];
    const float* mb1 = (const float*)d_in[4];
    const float* mw2 = (const float*)d_in[5];
    const float* mb2 = (const float*)d_in[6];
    const float* mwo = (const float*)d_in[7];
    const float* mbo = (const float*)d_in[8];
    const float* lw0 = (const float*)d_in[9];
    const float* lb0 = (const float*)d_in[10];
    const float* lw1 = (const float*)d_in[11];
    const float* lb1 = (const float*)d_in[12];
    const float* lw2 = (const float*)d_in[13];
    const float* lb2 = (const float*)d_in[14];
    const float* lwo = (const float*)d_in[15];
    const float* lbo = (const float*)d_in[16];
    float* out = (float*)d_out;

    cudaFuncSetAttribute(made_kernel, cudaFuncAttributeMaxDynamicSharedMemorySize, SMEM_BYTES);

    repack_kernel<<<(WP_TOTAL + 255) / 256, 256>>>(mw0, mw1, mw2, mwo, lw0, lw1, lw2, lwo);
    made_kernel<<<BATCH, 256, SMEM_BYTES>>>(x, mb0, mb1, mb2, mbo, lb0, lb1, lb2, lbo, out);
}

// round 2
// speedup vs baseline: 2.6450x; 2.6450x over previous
#include <cuda_runtime.h>
#include <math.h>
#include <stdint.h>

// Problem dims
#define BATCH 32
#define EPS   1e-12f

// ---------------- packed global weight layout (per net, 44800 floats) -------
//  w1 : [tap(5)][o(64)][i(68 pad)]   21760   @ 0
//  w2 : [tap(5)][o(64)][i(68 pad)]   21760   @ 21760
//  w0 : [tap(4)][o(64)][i(4)]         1024   @ 43520
//  wo : [o(64)][ch(4)]                 256   @ 44544
#define NET_STRIDE 44800
#define WP_TOTAL   (2 * NET_STRIDE)

__device__ float g_wp[WP_TOTAL];

// ---------------- shared memory layout (floats) -----------------------------
#define SM_W1   0        // 21760
#define SM_W2   21760    // 21760
#define SM_W0   43520    // 1024
#define SM_WO   44544    // 256
#define SM_H0   44800    // 4096  [64px][64]
#define SM_H1   48896    // 4096
#define SM_RED  52992    // 1024  [ih 4][a 4][o 64]
#define SM_Y    54016    // 256   [64px][4ch]
#define SM_X    54272    // 256
#define SM_LS   54528    // 256
#define SM_B0   54784    // 64
#define SM_B1   54848    // 64
#define SM_B2   54912    // 64
#define SM_BO   54976    // 4
#define SM_MLV  54980    // 64    [buf 2][net 2][a 4][ch 4]
#define SM_PART 55044    // 32    [a 4][half 2][ch 4]
#define SMEM_FLOATS 55080
#define SMEM_BYTES  (SMEM_FLOATS * 4)

// Mask-A taps (dr,dc): (-1,-1),(-1,0),(-1,1),(0,-1)
// Mask-B taps: A + center (0,0)
__global__ void repack_kernel(const float* __restrict__ mw0, const float* __restrict__ mw1,
                              const float* __restrict__ mw2, const float* __restrict__ mwo,
                              const float* __restrict__ lw0, const float* __restrict__ lw1,
                              const float* __restrict__ lw2, const float* __restrict__ lwo)
{
    int t = blockIdx.x * blockDim.x + threadIdx.x;
    if (t >= WP_TOTAL) return;
    const int krA[4] = {0,0,0,1}, kcA[4] = {0,1,2,0};
    const int krB[5] = {0,0,0,1,1}, kcB[5] = {0,1,2,0,1};
    int net = t / NET_STRIDE;
    int u   = t % NET_STRIDE;
    float v;
    if (u < 21760) {                       // w1: [tap][o][68]
        int tap = u / 4352, rem = u % 4352;
        int o = rem / 68, i = rem % 68;
        const float* w = net ? lw1 : mw1;
        v = (i < 64) ? w[((o * 64 + i) * 3 + krB[tap]) * 3 + kcB[tap]] : 0.f;
    } else if (u < 43520) {                // w2
        int u2 = u - 21760;
        int tap = u2 / 4352, rem = u2 % 4352;
        int o = rem / 68, i = rem % 68;
        const float* w = net ? lw2 : mw2;
        v = (i < 64) ? w[((o * 64 + i) * 3 + krB[tap]) * 3 + kcB[tap]] : 0.f;
    } else if (u < 44544) {                // w0: [tap][o][4]
        int u2 = u - 43520;
        int tap = u2 / 256, rem = u2 % 256;
        int o = rem / 4, i = rem % 4;
        const float* w = net ? lw0 : mw0;
        v = w[((o * 4 + i) * 3 + krA[tap]) * 3 + kcA[tap]];
    } else {                               // wo: [o][4]
        int u2 = u - 44544;
        int o = u2 / 4, ch = u2 % 4;
        const float* w = net ? lwo : mwo;
        v = w[ch * 64 + o];
    }
    g_wp[t] = v;
}

__device__ __forceinline__ float elu1(float v) {
    return v > 0.f ? v : (__expf(v) - 1.f);
}

__device__ __forceinline__ uint32_t smem_u32(const void* p) {
    uint32_t a;
    asm("{ .reg .u64 t; cvta.to.shared.u64 t, %1; cvt.u32.u64 %0, t; }" : "=r"(a) : "l"(p));
    return a;
}

__device__ __forceinline__ void st_remote_f32(uint32_t saddr, uint32_t rank, float v) {
    uint32_t raddr;
    asm volatile("mapa.shared::cluster.u32 %0, %1, %2;" : "=r"(raddr) : "r"(saddr), "r"(rank));
    asm volatile("st.shared::cluster.f32 [%0], %1;" :: "r"(raddr), "f"(v) : "memory");
}

__global__ void __cluster_dims__(2, 1, 1) __launch_bounds__(256, 1)
made_kernel(const float* __restrict__ x,
            const float* __restrict__ mb0, const float* __restrict__ mb1,
            const float* __restrict__ mb2, const float* __restrict__ mbo,
            const float* __restrict__ lb0, const float* __restrict__ lb1,
            const float* __restrict__ lb2, const float* __restrict__ lbo,
            float* __restrict__ out)
{
    extern __shared__ float sm[];
    const int tid = threadIdx.x;
    const int b = blockIdx.x >> 1;
    uint32_t net;
    asm("mov.u32 %0, %%cluster_ctarank;" : "=r"(net));

    // ---- startup: copy this net's weights into smem ----
    {
        const float4* src = (const float4*)(g_wp + net * NET_STRIDE);
        float4* dst = (float4*)sm;
        #pragma unroll 4
        for (int i = tid; i < NET_STRIDE / 4; i += 256)
            dst[i] = src[i];
    }
    // x -> [px][ch], y = 0
    {
        int ch = tid >> 6, p = tid & 63;
        sm[SM_X + p * 4 + ch] = x[b * 256 + tid];
        sm[SM_Y + tid] = 0.f;
    }
    if (tid < 64) {
        sm[SM_B0 + tid] = net ? lb0[tid] : mb0[tid];
        sm[SM_B1 + tid] = net ? lb1[tid] : mb1[tid];
        sm[SM_B2 + tid] = net ? lb2[tid] : mb2[tid];
    }
    if (tid < 4) sm[SM_BO + tid] = net ? lbo[tid] : mbo[tid];
    __syncthreads();

    const int dRA[4] = {-1,-1,-1, 0}, dCA[4] = {-1, 0, 1,-1};
    const int dRB[5] = {-1,-1,-1, 0, 0}, dCB[5] = {-1, 0, 1,-1, 0};

    const int o   = tid & 63;
    const int qa  = tid >> 6;          // role: pixel-slot in combine phases, i-quarter in GEMM phases
    const int ibase = qa * 16;
    const int lane = tid & 31;
    const uint32_t smbase = smem_u32(sm);

    for (int s = 0; s < 22; s++) {
        int rlo = (s - 6) > 0 ? (s - 6) / 2 : 0;
        int rhi = (s >> 1) < 7 ? (s >> 1) : 7;
        int npix = rhi - rlo + 1;

        // per-slot pixel coords (uniform across threads)
        int ra[4], ca[4], pa[4];
        #pragma unroll
        for (int a = 0; a < 4; a++) {
            ra[a] = rlo + a;
            ca[a] = s - 2 * ra[a];
            pa[a] = ra[a] * 8 + ca[a];
        }

        // ---------- layer 0 (mask A, 4 -> 64), thread (o, a) ----------
        if (qa < npix) {
            float acc = sm[SM_B0 + o];
            #pragma unroll
            for (int tap = 0; tap < 4; tap++) {
                int rr = ra[qa] + dRA[tap], cc = ca[qa] + dCA[tap];
                if (rr >= 0 && cc >= 0 && cc < 8) {
                    float4 w = *(const float4*)(sm + SM_W0 + (tap * 64 + o) * 4);
                    float4 y4 = *(const float4*)(sm + SM_Y + (rr * 8 + cc) * 4);
                    acc += w.x * y4.x + w.y * y4.y + w.z * y4.z + w.w * y4.w;
                }
            }
            sm[SM_H0 + pa[qa] * 64 + o] = elu1(acc);
        }
        __syncthreads();

        // ---------- layer 1 (mask B, 64 -> 64): thread (o, i-quarter) ----------
        {
            float a0 = 0.f, a1 = 0.f, a2 = 0.f, a3 = 0.f;
            #pragma unroll
            for (int tap = 0; tap < 5; tap++) {
                const float* wr = sm + SM_W1 + (tap * 64 + o) * 68 + ibase;
                float4 w0 = ((const float4*)wr)[0];
                float4 w1 = ((const float4*)wr)[1];
                float4 w2 = ((const float4*)wr)[2];
                float4 w3 = ((const float4*)wr)[3];
                #pragma unroll
                for (int a = 0; a < 4; a++) {
                    if (a < npix) {
                        int rr = ra[a] + dRB[tap], cc = ca[a] + dCB[tap];
                        if (rr >= 0 && cc >= 0 && cc < 8) {
                            const float* hp = sm + SM_H0 + (rr * 8 + cc) * 64 + ibase;
                            float4 h0 = ((const float4*)hp)[0];
                            float4 h1 = ((const float4*)hp)[1];
                            float4 h2 = ((const float4*)hp)[2];
                            float4 h3 = ((const float4*)hp)[3];
                            float t0 = w0.x*h0.x + w0.y*h0.y + w0.z*h0.z + w0.w*h0.w
                                     + w1.x*h1.x + w1.y*h1.y + w1.z*h1.z + w1.w*h1.w
                                     + w2.x*h2.x + w2.y*h2.y + w2.z*h2.z + w2.w*h2.w
                                     + w3.x*h3.x + w3.y*h3.y + w3.z*h3.z + w3.w*h3.w;
                            if (a == 0) a0 += t0; else if (a == 1) a1 += t0;
                            else if (a == 2) a2 += t0; else a3 += t0;
                        }
                    }
                }
            }
            if (0 < npix) sm[SM_RED + (qa * 4 + 0) * 64 + o] = a0;
            if (1 < npix) sm[SM_RED + (qa * 4 + 1) * 64 + o] = a1;
            if (2 < npix) sm[SM_RED + (qa * 4 + 2) * 64 + o] = a2;
            if (3 < npix) sm[SM_RED + (qa * 4 + 3) * 64 + o] = a3;
        }
        __syncthreads();

        // ---------- layer 1 combine ----------
        if (qa < npix) {
            float v = sm[SM_RED + (0 * 4 + qa) * 64 + o]
                    + sm[SM_RED + (1 * 4 + qa) * 64 + o]
                    + sm[SM_RED + (2 * 4 + qa) * 64 + o]
                    + sm[SM_RED + (3 * 4 + qa) * 64 + o]
                    + sm[SM_B1 + o];
            sm[SM_H1 + pa[qa] * 64 + o] = elu1(v);
        }
        __syncthreads();

        // ---------- layer 2 (mask B, 64 -> 64) ----------
        {
            float a0 = 0.f, a1 = 0.f, a2 = 0.f, a3 = 0.f;
            #pragma unroll
            for (int tap = 0; tap < 5; tap++) {
                const float* wr = sm + SM_W2 + (tap * 64 + o) * 68 + ibase;
                float4 w0 = ((const float4*)wr)[0];
                float4 w1 = ((const float4*)wr)[1];
                float4 w2 = ((const float4*)wr)[2];
                float4 w3 = ((const float4*)wr)[3];
                #pragma unroll
                for (int a = 0; a < 4; a++) {
                    if (a < npix) {
                        int rr = ra[a] + dRB[tap], cc = ca[a] + dCB[tap];
                        if (rr >= 0 && cc >= 0 && cc < 8) {
                            const float* hp = sm + SM_H1 + (rr * 8 + cc) * 64 + ibase;
                            float4 h0 = ((const float4*)hp)[0];
                            float4 h1 = ((const float4*)hp)[1];
                            float4 h2 = ((const float4*)hp)[2];
                            float4 h3 = ((const float4*)hp)[3];
                            float t0 = w0.x*h0.x + w0.y*h0.y + w0.z*h0.z + w0.w*h0.w
                                     + w1.x*h1.x + w1.y*h1.y + w1.z*h1.z + w1.w*h1.w
                                     + w2.x*h2.x + w2.y*h2.y + w2.z*h2.z + w2.w*h2.w
                                     + w3.x*h3.x + w3.y*h3.y + w3.z*h3.z + w3.w*h3.w;
                            if (a == 0) a0 += t0; else if (a == 1) a1 += t0;
                            else if (a == 2) a2 += t0; else a3 += t0;
                        }
                    }
                }
            }
            if (0 < npix) sm[SM_RED + (qa * 4 + 0) * 64 + o] = a0;
            if (1 < npix) sm[SM_RED + (qa * 4 + 1) * 64 + o] = a1;
            if (2 < npix) sm[SM_RED + (qa * 4 + 2) * 64 + o] = a2;
            if (3 < npix) sm[SM_RED + (qa * 4 + 3) * 64 + o] = a3;
        }
        __syncthreads();

        // ---------- layer 2 combine + 1x1 output conv ----------
        {
            float c0 = 0.f, c1 = 0.f, c2 = 0.f, c3 = 0.f;
            if (qa < npix) {
                float v = sm[SM_RED + (0 * 4 + qa) * 64 + o]
                        + sm[SM_RED + (1 * 4 + qa) * 64 + o]
                        + sm[SM_RED + (2 * 4 + qa) * 64 + o]
                        + sm[SM_RED + (3 * 4 + qa) * 64 + o]
                        + sm[SM_B2 + o];
                v = elu1(v);
                float4 w = *(const float4*)(sm + SM_WO + o * 4);
                c0 = v * w.x; c1 = v * w.y; c2 = v * w.z; c3 = v * w.w;
                #pragma unroll
                for (int off = 16; off >= 1; off >>= 1) {
                    c0 += __shfl_down_sync(0xffffffffu, c0, off);
                    c1 += __shfl_down_sync(0xffffffffu, c1, off);
                    c2 += __shfl_down_sync(0xffffffffu, c2, off);
                    c3 += __shfl_down_sync(0xffffffffu, c3, off);
                }
                if (lane == 0) {
                    int half = (o >> 5);
                    float* pp = sm + SM_PART + (qa * 2 + half) * 4;
                    pp[0] = c0; pp[1] = c1; pp[2] = c2; pp[3] = c3;
                }
            }
        }
        __syncthreads();

        // ---------- finalize mu/lv for this step, exchange with peer ----------
        int buf = s & 1;
        if (tid < npix * 4) {
            int a = tid >> 2, ch = tid & 3;
            float v = sm[SM_PART + (a * 2 + 0) * 4 + ch]
                    + sm[SM_PART + (a * 2 + 1) * 4 + ch]
                    + sm[SM_BO + ch];
            int off = SM_MLV + ((buf * 2 + (int)net) * 4 + a) * 4 + ch;
            sm[off] = v;
            st_remote_f32(smbase + (uint32_t)off * 4u, net ^ 1u, v);
        }
        asm volatile("barrier.cluster.arrive.aligned;" ::: "memory");
        asm volatile("barrier.cluster.wait.aligned;" ::: "memory");

        // ---------- y update (both CTAs, locally) ----------
        if (tid < npix * 4) {
            int a = tid >> 2, ch = tid & 3;
            int p = pa[a];
            float mu = sm[SM_MLV + ((buf * 2 + 0) * 4 + a) * 4 + ch];
            float ls = 0.5f * sm[SM_MLV + ((buf * 2 + 1) * 4 + a) * 4 + ch];
            float yv = (sm[SM_X + p * 4 + ch] - mu) / (__expf(ls) + EPS);
            sm[SM_Y + p * 4 + ch] = yv;
            sm[SM_LS + p * 4 + ch] = ls;
        }
        __syncthreads();
    }

    // ---- outputs ----
    if (net == 0) {
        // out y: [b][ch][p]
        out[b * 256 + tid] = sm[SM_Y + (tid & 63) * 4 + (tid >> 6)];
    } else {
        if (tid < 32) {
            float a = 0.f;
            #pragma unroll
            for (int k = 0; k < 8; k++) a += sm[SM_LS + tid * 8 + k];
            #pragma unroll
            for (int off = 16; off >= 1; off >>= 1)
                a += __shfl_down_sync(0xffffffffu, a, off);
            if (tid == 0) out[BATCH * 256 + b] = a;
        }
    }
}

extern "C" void kernel_launch(void* const* d_in, const int* in_sizes, int n_in,
                              void* d_out, int out_size)
{
    (void)in_sizes; (void)n_in; (void)out_size;
    const float* x   = (const float*)d_in[0];
    const float* mw0 = (const float*)d_in[1];
    const float* mb0 = (const float*)d_in[2];
    const float* mw1 = (const float*)d_in[3];
    const float* mb1 = (const float*)d_in[4];
    const float* mw2 = (const float*)d_in[5];
    const float* mb2 = (const float*)d_in[6];
    const float* mwo = (const float*)d_in[7];
    const float* mbo = (const float*)d_in[8];
    const float* lw0 = (const float*)d_in[9];
    const float* lb0 = (const float*)d_in[10];
    const float* lw1 = (const float*)d_in[11];
    const float* lb1 = (const float*)d_in[12];
    const float* lw2 = (const float*)d_in[13];
    const float* lb2 = (const float*)d_in[14];
    const float* lwo = (const float*)d_in[15];
    const float* lbo = (const float*)d_in[16];
    float* out = (float*)d_out;

    cudaFuncSetAttribute(made_kernel, cudaFuncAttributeMaxDynamicSharedMemorySize, SMEM_BYTES);

    repack_kernel<<<(WP_TOTAL + 255) / 256, 256>>>(mw0, mw1, mw2, mwo, lw0, lw1, lw2, lwo);
    made_kernel<<<2 * BATCH, 256, SMEM_BYTES>>>(x, mb0, mb1, mb2, mbo,
                                                lb0, lb1, lb2, lbo, out);
}

// round 3
// speedup vs baseline: 2.6548x; 1.0037x over previous
#include <cuda_runtime.h>
#include <math.h>
#include <stdint.h>

// Problem dims
#define BATCH 32
#define EPS   1e-12f

// ---------------- packed global weight layout (per net, 44800 floats) -------
//  w1 : [tap(5)][o(64)][i(68 pad)]   21760   @ 0
//  w2 : [tap(5)][o(64)][i(68 pad)]   21760   @ 21760
//  w0 : [tap(4)][o(64)][i(4)]         1024   @ 43520
//  wo : [o(64)][ch(4)]                 256   @ 44544
#define NET_STRIDE 44800
#define WP_TOTAL   (2 * NET_STRIDE)

__device__ float g_wp[WP_TOTAL];

// ---------------- shared memory layout (floats) -----------------------------
#define SM_W1   0        // 21760
#define SM_W2   21760    // 21760
#define SM_W0   43520    // 1024
#define SM_WO   44544    // 256
#define SM_H0   44800    // 4096  [64px][64]
#define SM_H1   48896    // 4096
#define SM_RED  52992    // 2048  [iq 8][a 4][o 64]
#define SM_Y    55040    // 256   [64px][4ch]
#define SM_X    55296    // 256
#define SM_LS   55552    // 256
#define SM_B0   55808    // 64
#define SM_B1   55872    // 64
#define SM_B2   55936    // 64
#define SM_BO   56000    // 4
#define SM_MLV  56004    // 32   [buf 2][a 4][ch 4]  (peer net's values land here)
#define SM_PART 56036    // 32   [a 4][half 2][ch 4]
#define SM_MBAR 56068    // 2    (8B, 8-byte aligned: 56068*4 = 224272)
#define SMEM_FLOATS 56072
#define SMEM_BYTES  (SMEM_FLOATS * 4)

// Mask-A taps (dr,dc): (-1,-1),(-1,0),(-1,1),(0,-1) ; Mask-B: A + (0,0)
__global__ void repack_kernel(const float* __restrict__ mw0, const float* __restrict__ mw1,
                              const float* __restrict__ mw2, const float* __restrict__ mwo,
                              const float* __restrict__ lw0, const float* __restrict__ lw1,
                              const float* __restrict__ lw2, const float* __restrict__ lwo)
{
    int t = blockIdx.x * blockDim.x + threadIdx.x;
    if (t >= WP_TOTAL) return;
    const int krA[4] = {0,0,0,1}, kcA[4] = {0,1,2,0};
    const int krB[5] = {0,0,0,1,1}, kcB[5] = {0,1,2,0,1};
    int net = t / NET_STRIDE;
    int u   = t % NET_STRIDE;
    float v;
    if (u < 21760) {                       // w1: [tap][o][68]
        int tap = u / 4352, rem = u % 4352;
        int o = rem / 68, i = rem % 68;
        const float* w = net ? lw1 : mw1;
        v = (i < 64) ? w[((o * 64 + i) * 3 + krB[tap]) * 3 + kcB[tap]] : 0.f;
    } else if (u < 43520) {                // w2
        int u2 = u - 21760;
        int tap = u2 / 4352, rem = u2 % 4352;
        int o = rem / 68, i = rem % 68;
        const float* w = net ? lw2 : mw2;
        v = (i < 64) ? w[((o * 64 + i) * 3 + krB[tap]) * 3 + kcB[tap]] : 0.f;
    } else if (u < 44544) {                // w0: [tap][o][4]
        int u2 = u - 43520;
        int tap = u2 / 256, rem = u2 % 256;
        int o = rem / 4, i = rem % 4;
        const float* w = net ? lw0 : mw0;
        v = w[((o * 4 + i) * 3 + krA[tap]) * 3 + kcA[tap]];
    } else {                               // wo: [o][4]
        int u2 = u - 44544;
        int o = u2 / 4, ch = u2 % 4;
        const float* w = net ? lwo : mwo;
        v = w[ch * 64 + o];
    }
    g_wp[t] = v;
}

__device__ __forceinline__ float elu1(float v) {
    return v > 0.f ? v : (__expf(v) - 1.f);
}

__device__ __forceinline__ uint32_t smem_u32(const void* p) {
    uint32_t a;
    asm("{ .reg .u64 t; cvta.to.shared.u64 t, %1; cvt.u32.u64 %0, t; }" : "=r"(a) : "l"(p));
    return a;
}

__device__ __forceinline__ void st_remote_f32(uint32_t saddr, uint32_t rank, float v) {
    uint32_t raddr;
    asm volatile("mapa.shared::cluster.u32 %0, %1, %2;" : "=r"(raddr) : "r"(saddr), "r"(rank));
    asm volatile("st.shared::cluster.f32 [%0], %1;" :: "r"(raddr), "f"(v) : "memory");
}

__device__ __forceinline__ void arrive_remote(uint32_t mbar_saddr, uint32_t rank) {
    asm volatile(
        "{\n\t"
        ".reg .b32 r;\n\t"
        "mapa.shared::cluster.u32 r, %0, %1;\n\t"
        "mbarrier.arrive.release.cluster.shared::cluster.b64 _, [r];\n\t"
        "}"
        :: "r"(mbar_saddr), "r"(rank) : "memory");
}

__device__ __forceinline__ void mbar_wait(uint32_t mbar_saddr, uint32_t parity) {
    asm volatile(
        "{\n\t"
        ".reg .pred P1;\n\t"
        "WAIT_LOOP_%=:\n\t"
        "mbarrier.try_wait.parity.acquire.cluster.shared::cta.b64 P1, [%0], %1, 0x989680;\n\t"
        "@P1 bra.uni WAIT_DONE_%=;\n\t"
        "bra.uni WAIT_LOOP_%=;\n\t"
        "WAIT_DONE_%=:\n\t"
        "}"
        :: "r"(mbar_saddr), "r"(parity) : "memory");
}

__device__ __forceinline__ void ffma2(unsigned long long& acc, unsigned long long w,
                                      unsigned long long h) {
    asm("fma.rn.f32x2 %0, %1, %2, %0;" : "+l"(acc) : "l"(w), "l"(h));
}

__device__ __forceinline__ float f2lo(unsigned long long v) {
    return __uint_as_float((uint32_t)v);
}
__device__ __forceinline__ float f2hi(unsigned long long v) {
    return __uint_as_float((uint32_t)(v >> 32));
}

__global__ void __cluster_dims__(2, 1, 1) __launch_bounds__(512, 1)
made_kernel(const float* __restrict__ x,
            const float* __restrict__ mb0, const float* __restrict__ mb1,
            const float* __restrict__ mb2, const float* __restrict__ mbo,
            const float* __restrict__ lb0, const float* __restrict__ lb1,
            const float* __restrict__ lb2, const float* __restrict__ lbo,
            float* __restrict__ out)
{
    extern __shared__ float sm[];
    const int tid = threadIdx.x;
    const int b = blockIdx.x >> 1;
    uint32_t net;
    asm("mov.u32 %0, %%cluster_ctarank;" : "=r"(net));
    const uint32_t peer = net ^ 1u;
    const uint32_t smbase = smem_u32(sm);
    const uint32_t mbar = smbase + SM_MBAR * 4u;

    // ---- startup ----
    {
        const float4* src = (const float4*)(g_wp + net * NET_STRIDE);
        float4* dst = (float4*)sm;
        #pragma unroll 4
        for (int i = tid; i < NET_STRIDE / 4; i += 512)
            dst[i] = src[i];
    }
    if (tid < 256) {
        int ch = tid >> 6, p = tid & 63;
        sm[SM_X + p * 4 + ch] = x[b * 256 + tid];
        sm[SM_Y + tid] = 0.f;
    }
    if (tid < 64) {
        sm[SM_B0 + tid] = net ? lb0[tid] : mb0[tid];
        sm[SM_B1 + tid] = net ? lb1[tid] : mb1[tid];
        sm[SM_B2 + tid] = net ? lb2[tid] : mb2[tid];
    }
    if (tid < 4) sm[SM_BO + tid] = net ? lbo[tid] : mbo[tid];
    if (tid == 0) {
        asm volatile("mbarrier.init.shared.b64 [%0], %1;" :: "r"(mbar), "r"(16) : "memory");
    }
    __syncthreads();
    asm volatile("barrier.cluster.arrive.aligned;" ::: "memory");
    asm volatile("barrier.cluster.wait.aligned;" ::: "memory");

    const int dRA[4] = {-1,-1,-1, 0}, dCA[4] = {-1, 0, 1,-1};
    const int dRB[5] = {-1,-1,-1, 0, 0}, dCB[5] = {-1, 0, 1,-1, 0};

    const int o     = tid & 63;
    const int iq    = tid >> 6;         // 0..7: i-chunk in GEMM phases / a-slot elsewhere
    const int ibase = iq * 8;
    const int lane  = tid & 31;

    for (int s = 0; s < 22; s++) {
        int rlo = (s - 6) > 0 ? (s - 6) / 2 : 0;
        int rhi = (s >> 1) < 7 ? (s >> 1) : 7;
        int npix = rhi - rlo + 1;

        int ra[4], ca[4], pa[4];
        #pragma unroll
        for (int a = 0; a < 4; a++) {
            ra[a] = rlo + a;
            ca[a] = s - 2 * ra[a];
            pa[a] = ra[a] * 8 + ca[a];
        }

        // ---------- layer 0 (mask A, 4 -> 64): thread (o, a=iq) ----------
        if (iq < npix) {
            float acc = sm[SM_B0 + o];
            #pragma unroll
            for (int tap = 0; tap < 4; tap++) {
                int rr = ra[iq] + dRA[tap], cc = ca[iq] + dCA[tap];
                if (rr >= 0 && cc >= 0 && cc < 8) {
                    float4 w = *(const float4*)(sm + SM_W0 + (tap * 64 + o) * 4);
                    float4 y4 = *(const float4*)(sm + SM_Y + (rr * 8 + cc) * 4);
                    acc += w.x * y4.x + w.y * y4.y + w.z * y4.z + w.w * y4.w;
                }
            }
            sm[SM_H0 + pa[iq] * 64 + o] = elu1(acc);
        }
        __syncthreads();

        // ---------- layer 1 GEMM (64 -> 64), thread (o, i-chunk) ----------
        {
            unsigned long long acc[4] = {0ull, 0ull, 0ull, 0ull};
            #pragma unroll
            for (int tap = 0; tap < 5; tap++) {
                const ulonglong2* wp2 =
                    (const ulonglong2*)(sm + SM_W1 + (tap * 64 + o) * 68 + ibase);
                ulonglong2 wA = wp2[0], wB = wp2[1];
                #pragma unroll
                for (int a = 0; a < 4; a++) {
                    int rr = ra[a] + dRB[tap], cc = ca[a] + dCB[tap];
                    if (a < npix && rr >= 0 && cc >= 0 && cc < 8) {
                        const ulonglong2* hp2 =
                            (const ulonglong2*)(sm + SM_H0 + (rr * 8 + cc) * 64 + ibase);
                        ulonglong2 hA = hp2[0], hB = hp2[1];
                        ffma2(acc[a], wA.x, hA.x);
                        ffma2(acc[a], wA.y, hA.y);
                        ffma2(acc[a], wB.x, hB.x);
                        ffma2(acc[a], wB.y, hB.y);
                    }
                }
            }
            #pragma unroll
            for (int a = 0; a < 4; a++)
                if (a < npix)
                    sm[SM_RED + (iq * 4 + a) * 64 + o] = f2lo(acc[a]) + f2hi(acc[a]);
        }
        __syncthreads();

        // ---------- layer 1 combine ----------
        if (tid < 256 && iq < npix) {
            float v = sm[SM_B1 + o];
            #pragma unroll
            for (int q = 0; q < 8; q++)
                v += sm[SM_RED + (q * 4 + iq) * 64 + o];
            sm[SM_H1 + pa[iq] * 64 + o] = elu1(v);
        }
        __syncthreads();

        // ---------- layer 2 GEMM ----------
        {
            unsigned long long acc[4] = {0ull, 0ull, 0ull, 0ull};
            #pragma unroll
            for (int tap = 0; tap < 5; tap++) {
                const ulonglong2* wp2 =
                    (const ulonglong2*)(sm + SM_W2 + (tap * 64 + o) * 68 + ibase);
                ulonglong2 wA = wp2[0], wB = wp2[1];
                #pragma unroll
                for (int a = 0; a < 4; a++) {
                    int rr = ra[a] + dRB[tap], cc = ca[a] + dCB[tap];
                    if (a < npix && rr >= 0 && cc >= 0 && cc < 8) {
                        const ulonglong2* hp2 =
                            (const ulonglong2*)(sm + SM_H1 + (rr * 8 + cc) * 64 + ibase);
                        ulonglong2 hA = hp2[0], hB = hp2[1];
                        ffma2(acc[a], wA.x, hA.x);
                        ffma2(acc[a], wA.y, hA.y);
                        ffma2(acc[a], wB.x, hB.x);
                        ffma2(acc[a], wB.y, hB.y);
                    }
                }
            }
            #pragma unroll
            for (int a = 0; a < 4; a++)
                if (a < npix)
                    sm[SM_RED + (iq * 4 + a) * 64 + o] = f2lo(acc[a]) + f2hi(acc[a]);
        }
        __syncthreads();

        // ---------- layer 2 combine + 1x1 output conv ----------
        if (tid < 256 && iq < npix) {
            float v = sm[SM_B2 + o];
            #pragma unroll
            for (int q = 0; q < 8; q++)
                v += sm[SM_RED + (q * 4 + iq) * 64 + o];
            v = elu1(v);
            float4 w = *(const float4*)(sm + SM_WO + o * 4);
            float c0 = v * w.x, c1 = v * w.y, c2 = v * w.z, c3 = v * w.w;
            #pragma unroll
            for (int off = 16; off >= 1; off >>= 1) {
                c0 += __shfl_down_sync(0xffffffffu, c0, off);
                c1 += __shfl_down_sync(0xffffffffu, c1, off);
                c2 += __shfl_down_sync(0xffffffffu, c2, off);
                c3 += __shfl_down_sync(0xffffffffu, c3, off);
            }
            if (lane == 0) {
                int half = o >> 5;
                float* pp = sm + SM_PART + (iq * 2 + half) * 4;
                pp[0] = c0; pp[1] = c1; pp[2] = c2; pp[3] = c3;
            }
        }
        __syncthreads();

        // ---------- finalize + peer exchange + y update (tid < 16 only) ----------
        int buf = s & 1;
        if (tid < 16) {
            int a = tid >> 2, ch = tid & 3;
            float v = 0.f;
            if (a < npix) {
                v = sm[SM_PART + (a * 2 + 0) * 4 + ch]
                  + sm[SM_PART + (a * 2 + 1) * 4 + ch]
                  + sm[SM_BO + ch];
                // send my net's value to the peer's MLV buffer
                uint32_t off = (uint32_t)(SM_MLV + buf * 16 + a * 4 + ch) * 4u;
                st_remote_f32(smbase + off, peer, v);
            }
            arrive_remote(mbar, peer);      // all 16 threads arrive on peer's barrier
            mbar_wait(mbar, (uint32_t)(s & 1));
            if (a < npix) {
                float pv = sm[SM_MLV + buf * 16 + a * 4 + ch]; // peer net's value
                float mu = net ? pv : v;
                float ls = 0.5f * (net ? v : pv);
                int p = pa[a];
                float yv = (sm[SM_X + p * 4 + ch] - mu) / (__expf(ls) + EPS);
                sm[SM_Y + p * 4 + ch] = yv;
                sm[SM_LS + p * 4 + ch] = ls;
            }
        }
        __syncthreads();
    }

    // ---- outputs ----
    if (net == 0) {
        if (tid < 256)
            out[b * 256 + tid] = sm[SM_Y + (tid & 63) * 4 + (tid >> 6)];
    } else {
        if (tid < 32) {
            float a = 0.f;
            #pragma unroll
            for (int k = 0; k < 8; k++) a += sm[SM_LS + tid * 8 + k];
            #pragma unroll
            for (int off = 16; off >= 1; off >>= 1)
                a += __shfl_down_sync(0xffffffffu, a, off);
            if (tid == 0) out[BATCH * 256 + b] = a;
        }
    }

    // safety: keep both CTAs resident until all DSMEM traffic is done
    asm volatile("barrier.cluster.arrive.aligned;" ::: "memory");
    asm volatile("barrier.cluster.wait.aligned;" ::: "memory");
}

extern "C" void kernel_launch(void* const* d_in, const int* in_sizes, int n_in,
                              void* d_out, int out_size)
{
    (void)in_sizes; (void)n_in; (void)out_size;
    const float* x   = (const float*)d_in[0];
    const float* mw0 = (const float*)d_in[1];
    const float* mb0 = (const float*)d_in[2];
    const float* mw1 = (const float*)d_in[3];
    const float* mb1 = (const float*)d_in[4];
    const float* mw2 = (const float*)d_in[5];
    const float* mb2 = (const float*)d_in[6];
    const float* mwo = (const float*)d_in[7];
    const float* mbo = (const float*)d_in[8];
    const float* lw0 = (const float*)d_in[9];
    const float* lb0 = (const float*)d_in[10];
    const float* lw1 = (const float*)d_in[11];
    const float* lb1 = (const float*)d_in[12];
    const float* lw2 = (const float*)d_in[13];
    const float* lb2 = (const float*)d_in[14];
    const float* lwo = (const float*)d_in[15];
    const float* lbo = (const float*)d_in[16];
    float* out = (float*)d_out;

    cudaFuncSetAttribute(made_kernel, cudaFuncAttributeMaxDynamicSharedMemorySize, SMEM_BYTES);

    repack_kernel<<<(WP_TOTAL + 255) / 256, 256>>>(mw0, mw1, mw2, mwo, lw0, lw1, lw2, lwo);
    made_kernel<<<2 * BATCH, 512, SMEM_BYTES>>>(x, mb0, mb1, mb2, mbo,
                                                lb0, lb1, lb2, lbo, out);
}